// round 9
// baseline (speedup 1.0000x reference)
#include <cuda_runtime.h>

// RX2: apply RX(theta_q) to each of 20 qubits of [16, 2^20] states.
// Stage at global stride 2^k uses qubit 19-k. Packed (re,im) u64 amplitudes,
// f32x2 FMA: 4 fma-pipe instrs per butterfly.
//
// Occupancy-first layout: 8 amps/thread, 512 threads, 4096-amp tiles,
// __launch_bounds__(512,3) -> ~48 warps/SM (vs 32 before).
//   Pass 1: stages 0..11  (contiguous 4096 tiles, 4 rounds, 3 exchanges)
//   Pass 2: stages 12..19 (256 strided rows x 16 contiguous, 3 rounds,
//           2 exchanges), in place.
// 4 groups of 4 batches pipelined on 2 forked streams (p1(g)->p2(g) per
// stream; groups overlap across streams; 32MB group intermediate in L2).

#define NQ 20
typedef unsigned long long u64;

__device__ __forceinline__ u64 pk2(float x, float y) {
    u64 v; asm("mov.b64 %0, {%1, %2};" : "=l"(v) : "f"(x), "f"(y)); return v;
}
__device__ __forceinline__ u64 swp(u64 v) {
    float x, y;
    asm("mov.b64 {%0, %1}, %2;" : "=f"(x), "=f"(y) : "l"(v));
    return pk2(y, x);
}
__device__ __forceinline__ u64 fma2(u64 a, u64 b, u64 c) {
    u64 d; asm("fma.rn.f32x2 %0, %1, %2, %3;" : "=l"(d) : "l"(a), "l"(b), "l"(c)); return d;
}
__device__ __forceinline__ u64 mul2(u64 a, u64 b) {
    u64 d; asm("mul.rn.f32x2 %0, %1, %2;" : "=l"(d) : "l"(a), "l"(b)); return d;
}

// a=(ar,ai), b=(br,bi); c2=(c,c), s2=(s,-s)
// na = c2*a + s2*swap(b) ; nb = c2*b + s2*swap(a)
__device__ __forceinline__ void bfly2(u64& a, u64& b, u64 c2, u64 s2) {
    u64 na = fma2(c2, a, mul2(s2, swp(b)));
    u64 nb = fma2(c2, b, mul2(s2, swp(a)));
    a = na; b = nb;
}

// -------------------------------------------------------------------------
// Pass 1: stages 0..11 (qubits 19..8). Tile = 4096 contiguous amplitudes.
// 512 threads, 8 amps/thread. Rounds: stages 0-2 / 3-5 / 6-8 / 9-11; the
// last round is fused with a fully-coalesced global store.
// Smem pad p = i + (i>>3) (conflict-free or 2-way worst per phase).
// -------------------------------------------------------------------------
__global__ __launch_bounds__(512, 3)
void rx_pass1(const float* __restrict__ phi,
              const float* __restrict__ thetas,
              u64* __restrict__ out, int b0)
{
    extern __shared__ u64 sm[];              // 4608 u64 (4096 + pad)
    __shared__ u64 c2B[12], s2B[12];
    __shared__ u64 cs0;                      // (c0, -s0) for real stage 0

    const int t    = threadIdx.x;
    const int b    = b0 + blockIdx.y;
    const int tile = blockIdx.x;
    const size_t base = ((size_t)b << 20) + ((size_t)tile << 12);

    if (t < 12) {
        float sv, cv;
        sincosf(0.5f * thetas[b * NQ + (19 - t)], &sv, &cv);
        c2B[t] = pk2(cv, cv);
        s2B[t] = pk2(sv, -sv);
        if (t == 0) cs0 = pk2(cv, -sv);
    }

    u64 amp[8];
    float rr[8];

    // ---- Round A: i = 8*t + j ; real input, evict-first ----
    const float4* pin = (const float4*)(phi + base + ((size_t)t << 3));
    {
        float4 v0 = __ldcs(pin);
        float4 v1 = __ldcs(pin + 1);
        rr[0] = v0.x; rr[1] = v0.y; rr[2] = v0.z; rr[3] = v0.w;
        rr[4] = v1.x; rr[5] = v1.y; rr[6] = v1.z; rr[7] = v1.w;
    }
    __syncthreads();   // coeffs visible

    // Stage 0 on real data: na = (c*ar, -s*br), nb = (c*br, -s*ar).
    {
        const u64 cs = cs0;
        #pragma unroll
        for (int j = 0; j < 8; j += 2) {
            amp[j]     = mul2(cs, pk2(rr[j],     rr[j + 1]));
            amp[j + 1] = mul2(cs, pk2(rr[j + 1], rr[j]));
        }
    }
    #pragma unroll
    for (int k = 1; k < 3; k++) {
        const u64 c2 = c2B[k], s2 = s2B[k];
        const int m = 1 << k;
        #pragma unroll
        for (int j = 0; j < 8; j++)
            if (!(j & m)) bfly2(amp[j], amp[j | m], c2, s2);
    }
    #pragma unroll
    for (int j = 0; j < 8; j++) {
        int i = (t << 3) + j;
        sm[i + (i >> 3)] = amp[j];
    }
    __syncthreads();

    // ---- Round B: i = (t&7) | (j<<3) | ((t>>3)<<6) ; stages 3..5 ----
    #pragma unroll
    for (int j = 0; j < 8; j++) {
        int i = (t & 7) | (j << 3) | ((t >> 3) << 6);
        amp[j] = sm[i + (i >> 3)];
    }
    #pragma unroll
    for (int k = 3; k < 6; k++) {
        const u64 c2 = c2B[k], s2 = s2B[k];
        const int m = 1 << (k - 3);
        #pragma unroll
        for (int j = 0; j < 8; j++)
            if (!(j & m)) bfly2(amp[j], amp[j | m], c2, s2);
    }
    #pragma unroll
    for (int j = 0; j < 8; j++) {           // rewrites exactly what it read
        int i = (t & 7) | (j << 3) | ((t >> 3) << 6);
        sm[i + (i >> 3)] = amp[j];
    }
    __syncthreads();

    // ---- Round C: i = (t&63) | (j<<6) | ((t>>6)<<9) ; stages 6..8 ----
    #pragma unroll
    for (int j = 0; j < 8; j++) {
        int i = (t & 63) | (j << 6) | ((t >> 6) << 9);
        amp[j] = sm[i + (i >> 3)];
    }
    #pragma unroll
    for (int k = 6; k < 9; k++) {
        const u64 c2 = c2B[k], s2 = s2B[k];
        const int m = 1 << (k - 6);
        #pragma unroll
        for (int j = 0; j < 8; j++)
            if (!(j & m)) bfly2(amp[j], amp[j | m], c2, s2);
    }
    #pragma unroll
    for (int j = 0; j < 8; j++) {
        int i = (t & 63) | (j << 6) | ((t >> 6) << 9);
        sm[i + (i >> 3)] = amp[j];
    }
    __syncthreads();

    // ---- Round D: i = t | (j<<9) ; stages 9..11, fused coalesced store ----
    #pragma unroll
    for (int j = 0; j < 8; j++) {
        int i = t | (j << 9);
        amp[j] = sm[i + (i >> 3)];
    }
    #pragma unroll
    for (int k = 9; k < 12; k++) {
        const u64 c2 = c2B[k], s2 = s2B[k];
        const int m = 1 << (k - 9);
        #pragma unroll
        for (int j = 0; j < 8; j++)
            if (!(j & m)) bfly2(amp[j], amp[j | m], c2, s2);
    }
    {
        u64* po = out + base;
        #pragma unroll
        for (int j = 0; j < 8; j++)          // stays in L2 for pass2
            po[t | (j << 9)] = amp[j];
    }
}

// -------------------------------------------------------------------------
// Pass 2: stages 12..19 (qubits 7..0), in place on out.
// Tile: h = 0..255 (global bits 12..19, stride 4096) x 16 contiguous
// (bits 0..3); chunk = bits 4..11. 512 threads, 8 amps/thread.
//   Round A: j = h bits 0..2 (stages 0..2)
//   Round B: j = h bits 3..5 (stages 3..5)
//   Round C: j bits 0,1 = h bits 6,7 (stages 6,7); j bit 2 = h bit 5
// Smem idx = (h<<4)|c : conflict-free per half-warp phase.
// -------------------------------------------------------------------------
__global__ __launch_bounds__(512, 3)
void rx_pass2(const float* __restrict__ thetas,
              u64* __restrict__ out, int b0)
{
    extern __shared__ u64 sm2[];             // 4096 u64
    __shared__ u64 c2B[8], s2B[8];

    const int t     = threadIdx.x;
    const int b     = b0 + blockIdx.y;
    const int chunk = blockIdx.x;            // global bits 4..11

    if (t < 8) {
        // stage m: global stride 2^(12+m) -> qubit 7-m
        float sv, cv;
        sincosf(0.5f * thetas[b * NQ + (7 - t)], &sv, &cv);
        c2B[t] = pk2(cv, cv);
        s2B[t] = pk2(sv, -sv);
    }

    u64* pg = out + ((size_t)b << 20) + ((size_t)chunk << 4);
    const int c  = t & 15;
    const int th = t >> 4;                   // 5 bits

    u64 amp[8];

    // ---- Round A: h = j | (th<<3) ; 128B-segment coalesced .cs loads ----
    #pragma unroll
    for (int j = 0; j < 8; j++) {
        int h = j | (th << 3);
        amp[j] = (u64)__ldcs((const long long*)(pg + (((size_t)h << 12) + c)));
    }
    __syncthreads();   // coeffs visible

    #pragma unroll
    for (int m = 0; m < 3; m++) {
        const u64 c2 = c2B[m], s2 = s2B[m];
        const int st = 1 << m;
        #pragma unroll
        for (int j = 0; j < 8; j++)
            if (!(j & st)) bfly2(amp[j], amp[j | st], c2, s2);
    }
    #pragma unroll
    for (int j = 0; j < 8; j++) {
        int h = j | (th << 3);
        sm2[(h << 4) + c] = amp[j];
    }
    __syncthreads();

    // ---- Round B: h = (th&7) | (j<<3) | ((th>>3)<<6) ; stages 3..5 ----
    #pragma unroll
    for (int j = 0; j < 8; j++) {
        int h = (th & 7) | (j << 3) | ((th >> 3) << 6);
        amp[j] = sm2[(h << 4) + c];
    }
    #pragma unroll
    for (int m = 3; m < 6; m++) {
        const u64 c2 = c2B[m], s2 = s2B[m];
        const int st = 1 << (m - 3);
        #pragma unroll
        for (int j = 0; j < 8; j++)
            if (!(j & st)) bfly2(amp[j], amp[j | st], c2, s2);
    }
    #pragma unroll
    for (int j = 0; j < 8; j++) {
        int h = (th & 7) | (j << 3) | ((th >> 3) << 6);
        sm2[(h << 4) + c] = amp[j];
    }
    __syncthreads();

    // ---- Round C: h = th | ((j>>2)<<5) | ((j&3)<<6) ; stages 6,7 ----
    #pragma unroll
    for (int j = 0; j < 8; j++) {
        int h = th | ((j >> 2) << 5) | ((j & 3) << 6);
        amp[j] = sm2[(h << 4) + c];
    }
    #pragma unroll
    for (int m = 6; m < 8; m++) {
        const u64 c2 = c2B[m], s2 = s2B[m];
        const int st = 1 << (m - 6);
        #pragma unroll
        for (int j = 0; j < 8; j++)
            if (!(j & st)) bfly2(amp[j], amp[j | st], c2, s2);
    }
    // ---- final store: streaming (evict-first) ----
    #pragma unroll
    for (int j = 0; j < 8; j++) {
        int h = th | ((j >> 2) << 5) | ((j & 3) << 6);
        __stcs((long long*)(pg + (((size_t)h << 12) + c)), (long long)amp[j]);
    }
}

extern "C" void kernel_launch(void* const* d_in, const int* in_sizes, int n_in,
                              void* d_out, int out_size)
{
    const float* phi    = (const float*)d_in[0];   // [16, 2^20] float32
    const float* thetas = (const float*)d_in[1];   // [16, 20]   float32
    u64* out = (u64*)d_out;                        // [16, 2^20] packed (re,im)

    const int SM1 = 4608 * (int)sizeof(u64);       // 36864 B
    const int SM2 = 4096 * (int)sizeof(u64);       // 32768 B
    cudaFuncSetAttribute(rx_pass1, cudaFuncAttributeMaxDynamicSharedMemorySize, SM1);
    cudaFuncSetAttribute(rx_pass2, cudaFuncAttributeMaxDynamicSharedMemorySize, SM2);

    // Host-side stream/event resources: EXACT round-7 config (2 streams,
    // 3 events) that passed the teardown memory check.
    static cudaStream_t s[2] = {nullptr, nullptr};
    static cudaEvent_t eRoot = nullptr, eDone[2] = {nullptr, nullptr};
    if (!s[0]) {
        cudaStreamCreateWithFlags(&s[0], cudaStreamNonBlocking);
        cudaStreamCreateWithFlags(&s[1], cudaStreamNonBlocking);
        cudaEventCreateWithFlags(&eRoot,    cudaEventDisableTiming);
        cudaEventCreateWithFlags(&eDone[0], cudaEventDisableTiming);
        cudaEventCreateWithFlags(&eDone[1], cudaEventDisableTiming);
    }

    // Fork both worker streams off the (capturing) launch stream.
    cudaEventRecord(eRoot, 0);
    cudaStreamWaitEvent(s[0], eRoot, 0);
    cudaStreamWaitEvent(s[1], eRoot, 0);

    // 4 groups of 4 batches; group g on stream g&1.
    for (int g = 0; g < 4; g++) {
        cudaStream_t st = s[g & 1];
        dim3 grid(256, 4);
        rx_pass1<<<grid, 512, SM1, st>>>(phi, thetas, out, g * 4);
        rx_pass2<<<grid, 512, SM2, st>>>(thetas, out, g * 4);
    }

    // Join back into the launch stream.
    cudaEventRecord(eDone[0], s[0]);
    cudaEventRecord(eDone[1], s[1]);
    cudaStreamWaitEvent(0, eDone[0], 0);
    cudaStreamWaitEvent(0, eDone[1], 0);
}

// round 10
// speedup vs baseline: 1.2255x; 1.2255x over previous
#include <cuda_runtime.h>

// RX2: apply RX(theta_q) to each of 20 qubits of [16, 2^20] states.
// Stage at global stride 2^k uses qubit 19-k. Packed (re,im) u64 amplitudes,
// f32x2 FMA: 4 fma-pipe instrs per butterfly.
//
// Latency-bound fix: small barrier domains. 256-thread CTAs, 16 amps/thread,
// 4096-amp tiles, 5 CTAs/SM -> 5 independent barrier groups hide each
// other's LDG/barrier waits.
//   Pass 1: stages 0..11  (contiguous tiles, 3 rounds, 2 exchanges)
//   Pass 2: stages 12..19 (256 rows x 16 contiguous, 2 rounds, 1 exchange)
// 4 groups of 4 batches on 2 forked streams (R7 host config, teardown-clean).

#define NQ 20
typedef unsigned long long u64;

__device__ __forceinline__ u64 pk2(float x, float y) {
    u64 v; asm("mov.b64 %0, {%1, %2};" : "=l"(v) : "f"(x), "f"(y)); return v;
}
__device__ __forceinline__ u64 swp(u64 v) {
    float x, y;
    asm("mov.b64 {%0, %1}, %2;" : "=f"(x), "=f"(y) : "l"(v));
    return pk2(y, x);
}
__device__ __forceinline__ u64 fma2(u64 a, u64 b, u64 c) {
    u64 d; asm("fma.rn.f32x2 %0, %1, %2, %3;" : "=l"(d) : "l"(a), "l"(b), "l"(c)); return d;
}
__device__ __forceinline__ u64 mul2(u64 a, u64 b) {
    u64 d; asm("mul.rn.f32x2 %0, %1, %2;" : "=l"(d) : "l"(a), "l"(b)); return d;
}

// a=(ar,ai), b=(br,bi); c2=(c,c), s2=(s,-s)
// na = c2*a + s2*swap(b) ; nb = c2*b + s2*swap(a)
__device__ __forceinline__ void bfly2(u64& a, u64& b, u64 c2, u64 s2) {
    u64 na = fma2(c2, a, mul2(s2, swp(b)));
    u64 nb = fma2(c2, b, mul2(s2, swp(a)));
    a = na; b = nb;
}

// -------------------------------------------------------------------------
// Pass 1: stages 0..11 (qubits 19..8). Tile = 4096 contiguous amplitudes.
// 256 threads, 16 amps/thread. Rounds: stages 0-3 / 4-7 / 8-11; the last
// round is fused with a fully-coalesced global store.
// Smem pad p = i + (i>>4): all phases conflict-free.
// -------------------------------------------------------------------------
__global__ __launch_bounds__(256, 5)
void rx_pass1(const float* __restrict__ phi,
              const float* __restrict__ thetas,
              u64* __restrict__ out, int b0)
{
    extern __shared__ u64 sm[];              // 4352 u64 (4096 + pad)
    __shared__ u64 c2B[12], s2B[12];
    __shared__ u64 cs0;                      // (c0, -s0) for real stage 0

    const int t    = threadIdx.x;            // 0..255
    const int b    = b0 + blockIdx.y;
    const int tile = blockIdx.x;
    const size_t base = ((size_t)b << 20) + ((size_t)tile << 12);

    // ---- issue global loads first (overlap with coeff sincos + barrier) ----
    float rr[16];
    const float4* pin = (const float4*)(phi + base + ((size_t)t << 4));
    #pragma unroll
    for (int q = 0; q < 4; q++) {
        float4 v = __ldcs(pin + q);
        rr[4*q+0] = v.x; rr[4*q+1] = v.y; rr[4*q+2] = v.z; rr[4*q+3] = v.w;
    }

    if (t < 12) {
        float sv, cv;
        sincosf(0.5f * thetas[b * NQ + (19 - t)], &sv, &cv);
        c2B[t] = pk2(cv, cv);
        s2B[t] = pk2(sv, -sv);
        if (t == 0) cs0 = pk2(cv, -sv);
    }
    __syncthreads();   // coeffs visible

    u64 amp[16];

    // ---- Round A: i = (t<<4)+j ; stages 0..3 (stage 0 on real data) ----
    {
        const u64 cs = cs0;
        #pragma unroll
        for (int j = 0; j < 16; j += 2) {
            // na = (c*ar, -s*br), nb = (c*br, -s*ar)
            amp[j]     = mul2(cs, pk2(rr[j],     rr[j + 1]));
            amp[j + 1] = mul2(cs, pk2(rr[j + 1], rr[j]));
        }
    }
    #pragma unroll
    for (int k = 1; k < 4; k++) {
        const u64 c2 = c2B[k], s2 = s2B[k];
        const int m = 1 << k;
        #pragma unroll
        for (int j = 0; j < 16; j++)
            if (!(j & m)) bfly2(amp[j], amp[j | m], c2, s2);
    }
    #pragma unroll
    for (int j = 0; j < 16; j++) {
        int i = (t << 4) + j;
        sm[i + (i >> 4)] = amp[j];
    }
    __syncthreads();

    // ---- Round B: i = (t&15) | (j<<4) | ((t>>4)<<8) ; stages 4..7 ----
    #pragma unroll
    for (int j = 0; j < 16; j++) {
        int i = (t & 15) | (j << 4) | ((t >> 4) << 8);
        amp[j] = sm[i + (i >> 4)];
    }
    #pragma unroll
    for (int k = 4; k < 8; k++) {
        const u64 c2 = c2B[k], s2 = s2B[k];
        const int m = 1 << (k - 4);
        #pragma unroll
        for (int j = 0; j < 16; j++)
            if (!(j & m)) bfly2(amp[j], amp[j | m], c2, s2);
    }
    #pragma unroll
    for (int j = 0; j < 16; j++) {           // rewrites exactly what it read
        int i = (t & 15) | (j << 4) | ((t >> 4) << 8);
        sm[i + (i >> 4)] = amp[j];
    }
    __syncthreads();

    // ---- Round C: i = t | (j<<8) ; stages 8..11, fused coalesced store ----
    #pragma unroll
    for (int j = 0; j < 16; j++) {
        int i = t | (j << 8);
        amp[j] = sm[i + (i >> 4)];
    }
    #pragma unroll
    for (int k = 8; k < 12; k++) {
        const u64 c2 = c2B[k], s2 = s2B[k];
        const int m = 1 << (k - 8);
        #pragma unroll
        for (int j = 0; j < 16; j++)
            if (!(j & m)) bfly2(amp[j], amp[j | m], c2, s2);
    }
    {
        u64* po = out + base;
        #pragma unroll
        for (int j = 0; j < 16; j++)         // stays in L2 for pass2
            po[t | (j << 8)] = amp[j];
    }
}

// -------------------------------------------------------------------------
// Pass 2: stages 12..19 (qubits 7..0), in place on out.
// Tile: h = 0..255 (global bits 12..19, stride 4096) x 16 contiguous
// (bits 0..3); chunk = global bits 4..11. 256 threads, 16 amps/thread,
// ONE smem exchange. c = t&15 rides the lanes: 128B-per-row coalescing,
// conflict-free smem.
//   Round A: j = h bits 0..3 (stages 0..3)
//   Round B: j = h bits 4..7 (stages 4..7)
// -------------------------------------------------------------------------
__global__ __launch_bounds__(256, 5)
void rx_pass2(const float* __restrict__ thetas,
              u64* __restrict__ out, int b0)
{
    extern __shared__ u64 sm2[];             // 4096 u64
    __shared__ u64 c2B[8], s2B[8];

    const int t     = threadIdx.x;           // 0..255
    const int b     = b0 + blockIdx.y;
    const int chunk = blockIdx.x;            // global bits 4..11

    u64* pg = out + ((size_t)b << 20) + ((size_t)chunk << 4);
    const int c  = t & 15;
    const int th = t >> 4;                   // 0..15

    // ---- issue global loads first: h = j | (th<<4) ----
    u64 amp[16];
    #pragma unroll
    for (int j = 0; j < 16; j++) {
        int h = j | (th << 4);
        amp[j] = (u64)__ldcs((const long long*)(pg + (((size_t)h << 12) + c)));
    }

    if (t < 8) {
        // stage m: global stride 2^(12+m) -> qubit 7-m
        float sv, cv;
        sincosf(0.5f * thetas[b * NQ + (7 - t)], &sv, &cv);
        c2B[t] = pk2(cv, cv);
        s2B[t] = pk2(sv, -sv);
    }
    __syncthreads();   // coeffs visible

    // ---- Round A: stages 0..3 on j = h bits 0..3 ----
    #pragma unroll
    for (int m = 0; m < 4; m++) {
        const u64 c2 = c2B[m], s2 = s2B[m];
        const int st = 1 << m;
        #pragma unroll
        for (int j = 0; j < 16; j++)
            if (!(j & st)) bfly2(amp[j], amp[j | st], c2, s2);
    }
    #pragma unroll
    for (int j = 0; j < 16; j++) {
        int h = j | (th << 4);
        sm2[(h << 4) + c] = amp[j];
    }
    __syncthreads();

    // ---- Round B: h = th | (j<<4) ; stages 4..7 ----
    #pragma unroll
    for (int j = 0; j < 16; j++) {
        int h = th | (j << 4);
        amp[j] = sm2[(h << 4) + c];
    }
    #pragma unroll
    for (int m = 4; m < 8; m++) {
        const u64 c2 = c2B[m], s2 = s2B[m];
        const int st = 1 << (m - 4);
        #pragma unroll
        for (int j = 0; j < 16; j++)
            if (!(j & st)) bfly2(amp[j], amp[j | st], c2, s2);
    }
    // ---- final store: streaming (evict-first), coalesced ----
    #pragma unroll
    for (int j = 0; j < 16; j++) {
        int h = th | (j << 4);
        __stcs((long long*)(pg + (((size_t)h << 12) + c)), (long long)amp[j]);
    }
}

extern "C" void kernel_launch(void* const* d_in, const int* in_sizes, int n_in,
                              void* d_out, int out_size)
{
    const float* phi    = (const float*)d_in[0];   // [16, 2^20] float32
    const float* thetas = (const float*)d_in[1];   // [16, 20]   float32
    u64* out = (u64*)d_out;                        // [16, 2^20] packed (re,im)

    const int SM1 = 4352 * (int)sizeof(u64);       // 34816 B
    const int SM2 = 4096 * (int)sizeof(u64);       // 32768 B
    cudaFuncSetAttribute(rx_pass1, cudaFuncAttributeMaxDynamicSharedMemorySize, SM1);
    cudaFuncSetAttribute(rx_pass2, cudaFuncAttributeMaxDynamicSharedMemorySize, SM2);

    // Host-side stream/event resources: EXACT round-7 config (2 streams,
    // 3 events) that passed the teardown memory check.
    static cudaStream_t s[2] = {nullptr, nullptr};
    static cudaEvent_t eRoot = nullptr, eDone[2] = {nullptr, nullptr};
    if (!s[0]) {
        cudaStreamCreateWithFlags(&s[0], cudaStreamNonBlocking);
        cudaStreamCreateWithFlags(&s[1], cudaStreamNonBlocking);
        cudaEventCreateWithFlags(&eRoot,    cudaEventDisableTiming);
        cudaEventCreateWithFlags(&eDone[0], cudaEventDisableTiming);
        cudaEventCreateWithFlags(&eDone[1], cudaEventDisableTiming);
    }

    // Fork both worker streams off the (capturing) launch stream.
    cudaEventRecord(eRoot, 0);
    cudaStreamWaitEvent(s[0], eRoot, 0);
    cudaStreamWaitEvent(s[1], eRoot, 0);

    // 4 groups of 4 batches; group g on stream g&1.
    for (int g = 0; g < 4; g++) {
        cudaStream_t st = s[g & 1];
        dim3 grid(256, 4);
        rx_pass1<<<grid, 256, SM1, st>>>(phi, thetas, out, g * 4);
        rx_pass2<<<grid, 256, SM2, st>>>(thetas, out, g * 4);
    }

    // Join back into the launch stream.
    cudaEventRecord(eDone[0], s[0]);
    cudaEventRecord(eDone[1], s[1]);
    cudaStreamWaitEvent(0, eDone[0], 0);
    cudaStreamWaitEvent(0, eDone[1], 0);
}